// round 1
// baseline (speedup 1.0000x reference)
#include <cuda_runtime.h>
#include <cuda_bf16.h>
#include <cstdint>

#define BB    4
#define LQ    256
#define LK    2048
#define HIDD  1024
#define NH    16
#define DD    64

#define CENTER_C      72.21632f      /* 64 * 1.12838 */
#define INV_SCALING_C 0.14662718f    /* 1 / (sqrt(0.72676) * 8) */

typedef unsigned long long u64;
#define ABSM 0x7FFFFFFF7FFFFFFFULL

__device__ __forceinline__ u64 fadd2(u64 a, u64 b) {
    u64 r; asm("add.rn.f32x2 %0, %1, %2;" : "=l"(r) : "l"(a), "l"(b)); return r;
}
__device__ __forceinline__ u64 ffma2(u64 a, u64 b, u64 c) {
    u64 r; asm("fma.rn.f32x2 %0, %1, %2, %3;" : "=l"(r) : "l"(a), "l"(b), "l"(c)); return r;
}
__device__ __forceinline__ float2 upk2(u64 a) {
    float2 f; asm("mov.b64 {%0, %1}, %2;" : "=f"(f.x), "=f"(f.y) : "l"(a)); return f;
}

// ---------------------------------------------------------------------------
// Kernel 1: L1-distance logits.
//   grid (LQ/32, NH, BB), block 256 (8 warps). Each CTA: 32 q rows of one (b,h).
//   Each warp: 4 q rows; lanes cover 32 k's; K streamed in 128-row smem chunks
//   (XOR-swizzled float4 layout for conflict-free LDS.128).
//   Distance math in packed f32x2 (FADD2 + LOP3-abs + FFMA2).
// ---------------------------------------------------------------------------
__global__ __launch_bounds__(256) void k_logits(
    const float* __restrict__ Qg, const float* __restrict__ Kg,
    const float* __restrict__ diag, float* __restrict__ attn)
{
    extern __shared__ float smem[];
    float4* kbuf = (float4*)smem;            // 2048 float4 (128 rows x 16, swizzled)
    float*  qbuf = smem + 8192;              // 32 q rows x 64 floats (negated)
    float*  dbuf = qbuf + 2048;              // 64 floats (diag for head h)

    const int b  = blockIdx.z, h = blockIdx.y;
    const int q0 = blockIdx.x * 32;
    const int tid = threadIdx.x, w = tid >> 5, lane = tid & 31;

    if (tid < 16)
        ((float4*)dbuf)[tid] = ((const float4*)(diag + h * DD))[tid];

    for (int i = tid; i < 512; i += 256) {           // 32 rows x 16 f4
        int qr = i >> 4, g = i & 15;
        float4 v = ((const float4*)(Qg + ((size_t)(b * LQ + q0 + qr)) * HIDD + h * DD))[g];
        ((float4*)qbuf)[qr * 16 + g] = make_float4(-v.x, -v.y, -v.z, -v.w);
    }
    __syncthreads();

    const ulonglong2* kb2 = (const ulonglong2*)kbuf;
    const ulonglong2* qb2 = (const ulonglong2*)qbuf;
    const ulonglong2* db2 = (const ulonglong2*)dbuf;
    const int qb = w * 4;
    const int s  = lane & 7;

    for (int kc = 0; kc < LK; kc += 128) {
        for (int i = tid; i < 2048; i += 256) {      // 128 rows x 16 f4
            int kr = i >> 4, g = i & 15;
            float4 v = ((const float4*)(Kg + ((size_t)(b * LK + kc + kr)) * HIDD + h * DD))[g];
            kbuf[kr * 16 + (g ^ (kr & 7))] = v;      // XOR swizzle
        }
        __syncthreads();

        u64 acc[4][4];
        #pragma unroll
        for (int q = 0; q < 4; q++)
            #pragma unroll
            for (int kk = 0; kk < 4; kk++) acc[q][kk] = 0ull;

        for (int g = 0; g < 16; g++) {
            ulonglong2 dv = db2[g];
            ulonglong2 qv[4];
            #pragma unroll
            for (int q = 0; q < 4; q++) qv[q] = qb2[(qb + q) * 16 + g];
            #pragma unroll
            for (int kk = 0; kk < 4; kk++) {
                ulonglong2 kv = kb2[(kk * 32 + lane) * 16 + (g ^ s)];
                #pragma unroll
                for (int q = 0; q < 4; q++) {
                    u64 t0 = fadd2(kv.x, qv[q].x) & ABSM;   // |k - q| (q pre-negated)
                    u64 t1 = fadd2(kv.y, qv[q].y) & ABSM;
                    acc[q][kk] = ffma2(dv.x, t0, acc[q][kk]);
                    acc[q][kk] = ffma2(dv.y, t1, acc[q][kk]);
                }
            }
        }

        #pragma unroll
        for (int q = 0; q < 4; q++) {
            size_t base = (((size_t)(b * NH + h)) * LQ + (q0 + qb + q)) * (size_t)LK + kc;
            #pragma unroll
            for (int kk = 0; kk < 4; kk++) {
                float2 a = upk2(acc[q][kk]);
                float dist = a.x + a.y;
                attn[base + kk * 32 + lane] = (CENTER_C - dist) * INV_SCALING_C;
            }
        }
        __syncthreads();
    }
}

// ---------------------------------------------------------------------------
// Kernel 2: softmax + P write + P@V.
//   Same grid. Phase 1: per-row max & exp-sum (each warp owns 4 rows).
//   Phase 2: per 128-k chunk: normalize+store P (smem + gmem), V transposed in
//   smem (stride 130 to kill conflicts), P@V with packed f32x2 over k-pairs.
// ---------------------------------------------------------------------------
__global__ __launch_bounds__(256) void k_softpv(
    float* __restrict__ attn, const float* __restrict__ Vg,
    float* __restrict__ out0)
{
    extern __shared__ float smem[];
    float* vT  = smem;                 // 64 x 130 floats
    float* psm = smem + 64 * 130;      // 32 q x 128 k
    float* smM = psm + 32 * 128;       // 32
    float* smI = smM + 32;             // 32

    const int b  = blockIdx.z, h = blockIdx.y;
    const int q0 = blockIdx.x * 32;
    const int tid = threadIdx.x, w = tid >> 5, lane = tid & 31;
    const int qb = w * 4;

    // Phase 1: row max + 1/sum(exp)
    for (int q = 0; q < 4; q++) {
        const float* lrow = attn + (((size_t)(b * NH + h)) * LQ + (q0 + qb + q)) * (size_t)LK;
        float m = -1e30f;
        #pragma unroll 8
        for (int i = 0; i < 64; i++) m = fmaxf(m, lrow[i * 32 + lane]);
        #pragma unroll
        for (int o = 16; o > 0; o >>= 1) m = fmaxf(m, __shfl_xor_sync(0xffffffffu, m, o));
        float ssum = 0.f;
        #pragma unroll 8
        for (int i = 0; i < 64; i++) ssum += __expf(lrow[i * 32 + lane] - m);
        #pragma unroll
        for (int o = 16; o > 0; o >>= 1) ssum += __shfl_xor_sync(0xffffffffu, ssum, o);
        if (lane == 0) { smM[qb + q] = m; smI[qb + q] = 1.f / ssum; }
    }
    __syncthreads();

    u64 acc[4][2];
    #pragma unroll
    for (int q = 0; q < 4; q++) { acc[q][0] = 0ull; acc[q][1] = 0ull; }

    for (int kc = 0; kc < LK; kc += 128) {
        // load V chunk transposed: vT[d][k], row stride 130
        for (int i = tid; i < 2048; i += 256) {
            int kr = i >> 4, g = i & 15;
            float4 v = ((const float4*)(Vg + ((size_t)(b * LK + kc + kr)) * HIDD + h * DD))[g];
            float* dst = vT + kr;
            dst[(4 * g + 0) * 130] = v.x;
            dst[(4 * g + 1) * 130] = v.y;
            dst[(4 * g + 2) * 130] = v.z;
            dst[(4 * g + 3) * 130] = v.w;
        }
        // compute probabilities for this chunk, stash in smem + write to gmem
        for (int i = tid; i < 4096; i += 256) {
            int q = i >> 7, k = i & 127;
            size_t idx = (((size_t)(b * NH + h)) * LQ + (q0 + q)) * (size_t)LK + kc + k;
            float p = __expf(attn[idx] - smM[q]) * smI[q];
            psm[q * 128 + k] = p;
            attn[idx] = p;
        }
        __syncthreads();

        // P @ V: lane = d (two halves d=lane, d=lane+32), packed over k-pairs
        #pragma unroll 4
        for (int k2 = 0; k2 < 64; k2++) {
            u64 v0 = *(const u64*)(vT + lane * 130 + 2 * k2);
            u64 v1 = *(const u64*)(vT + (lane + 32) * 130 + 2 * k2);
            #pragma unroll
            for (int q = 0; q < 4; q++) {
                u64 pp = *(const u64*)(psm + (qb + q) * 128 + 2 * k2);
                acc[q][0] = ffma2(pp, v0, acc[q][0]);
                acc[q][1] = ffma2(pp, v1, acc[q][1]);
            }
        }
        __syncthreads();
    }

    #pragma unroll
    for (int q = 0; q < 4; q++) {
        float2 a0 = upk2(acc[q][0]);
        float2 a1 = upk2(acc[q][1]);
        size_t ob = ((size_t)(b * LQ + q0 + qb + q)) * HIDD + h * DD;
        out0[ob + lane]      = a0.x + a0.y;
        out0[ob + 32 + lane] = a1.x + a1.y;
    }
}

#define SMEM1 ((2048 * 4 + 2048 + 64) * 4)          /* 41216 B */
#define SMEM2 ((64 * 130 + 32 * 128 + 64) * 4)      /* 49920 B */

extern "C" void kernel_launch(void* const* d_in, const int* in_sizes, int n_in,
                              void* d_out, int out_size)
{
    const float* Qg = (const float*)d_in[0];
    const float* Kg = (const float*)d_in[1];
    const float* Vg = (const float*)d_in[2];
    const float* dg = (const float*)d_in[3];

    float* out0 = (float*)d_out;
    // reference returns (output, attention): assume flattened concat
    float* attn = out0 + (size_t)BB * LQ * HIDD;

    cudaFuncSetAttribute(k_logits, cudaFuncAttributeMaxDynamicSharedMemorySize, SMEM1);
    cudaFuncSetAttribute(k_softpv, cudaFuncAttributeMaxDynamicSharedMemorySize, SMEM2);

    dim3 grid(LQ / 32, NH, BB);
    k_logits<<<grid, 256, SMEM1>>>(Qg, Kg, dg, attn);
    k_softpv<<<grid, 256, SMEM2>>>(attn, Vg, out0);
}

// round 2
// speedup vs baseline: 1.1196x; 1.1196x over previous
#include <cuda_runtime.h>
#include <cuda_bf16.h>
#include <cstdint>

#define BB    4
#define LQ    256
#define LK    2048
#define HIDD  1024
#define NH    16
#define DD    64

#define CENTER_C      72.21632f      /* 64 * 1.12838 */
#define INV_SCALING_C 0.14662718f    /* 1 / (sqrt(0.72676) * 8) */

typedef unsigned long long u64;
#define ABSM 0x7FFFFFFF7FFFFFFFULL

__device__ float g_rsum[BB * NH * LQ];                    // 1/sum(exp) per q row
__device__ float g_VT[(size_t)BB * NH * DD * LK];         // V transposed [b,h,d,k]

__device__ __forceinline__ u64 fadd2(u64 a, u64 b) {
    u64 r; asm("add.rn.f32x2 %0, %1, %2;" : "=l"(r) : "l"(a), "l"(b)); return r;
}
__device__ __forceinline__ u64 ffma2(u64 a, u64 b, u64 c) {
    u64 r; asm("fma.rn.f32x2 %0, %1, %2, %3;" : "=l"(r) : "l"(a), "l"(b), "l"(c)); return r;
}
__device__ __forceinline__ float2 upk2(u64 a) {
    float2 f; asm("mov.b64 {%0, %1}, %2;" : "=f"(f.x), "=f"(f.y) : "l"(a)); return f;
}
__device__ __forceinline__ void cp16(uint32_t dst, const void* src) {
    asm volatile("cp.async.cg.shared.global [%0], [%1], 16;" :: "r"(dst), "l"(src));
}

// ---------------------------------------------------------------------------
// Kernel 0: transpose V -> VT[b,h,d,k] so kernel 2 can load d-rows coalesced.
//   grid (LK/64, BB*NH), block 256. 64x64 tile via padded smem.
// ---------------------------------------------------------------------------
__global__ __launch_bounds__(256) void k_vtrans(const float* __restrict__ Vg)
{
    __shared__ float t[64][65];
    const int bh = blockIdx.y, b = bh >> 4, h = bh & 15;
    const int k0 = blockIdx.x * 64;
    const int tid = threadIdx.x;
    #pragma unroll
    for (int r = 0; r < 4; r++) {
        int i = tid + 256 * r; int kr = i >> 4, g = i & 15;
        float4 v = *(const float4*)(Vg + ((size_t)(b * LK + k0 + kr)) * HIDD + h * DD + 4 * g);
        t[kr][4 * g + 0] = v.x; t[kr][4 * g + 1] = v.y;
        t[kr][4 * g + 2] = v.z; t[kr][4 * g + 3] = v.w;
    }
    __syncthreads();
    #pragma unroll
    for (int r = 0; r < 4; r++) {
        int i = tid + 256 * r; int d = i >> 4, g = i & 15;
        float4 o = make_float4(t[4 * g + 0][d], t[4 * g + 1][d], t[4 * g + 2][d], t[4 * g + 3][d]);
        *(float4*)(g_VT + ((size_t)(bh * DD + d)) * LK + k0 + 4 * g) = o;
    }
}

// ---------------------------------------------------------------------------
// Kernel 1: L1-distance -> exp(logit) + per-row sum.
//   grid (LQ/32, NH, BB), block 256. Warp owns 4 q rows across ALL k, so the
//   softmax denominator accumulates in registers. K streamed with cp.async
//   double buffering (XOR-swizzled float4 layout). Math in packed f32x2.
//   Writes exp(logit) to attn; writes 1/sum to g_rsum.
// ---------------------------------------------------------------------------
__global__ __launch_bounds__(256) void k_logits(
    const float* __restrict__ Qg, const float* __restrict__ Kg,
    const float* __restrict__ diag, float* __restrict__ attn)
{
    extern __shared__ float smem[];
    // [0..8191] kbuf0, [8192..16383] kbuf1, [16384..18431] qbuf, [18432..18495] dbuf
    float* qbuf = smem + 16384;
    float* dbuf = qbuf + 2048;

    const int b  = blockIdx.z, h = blockIdx.y;
    const int q0 = blockIdx.x * 32;
    const int tid = threadIdx.x, w = tid >> 5, lane = tid & 31;
    const uint32_t sbase = (uint32_t)__cvta_generic_to_shared(smem);

    if (tid < 16)
        ((float4*)dbuf)[tid] = ((const float4*)(diag + h * DD))[tid];

    for (int i = tid; i < 512; i += 256) {           // 32 q rows x 16 f4, negated
        int qr = i >> 4, g = i & 15;
        float4 v = ((const float4*)(Qg + ((size_t)(b * LQ + q0 + qr)) * HIDD + h * DD))[g];
        ((float4*)qbuf)[qr * 16 + g] = make_float4(-v.x, -v.y, -v.z, -v.w);
    }

    // prefetch chunk 0 into buffer 0
    #pragma unroll
    for (int r = 0; r < 8; r++) {
        int i = tid + 256 * r; int kr = i >> 4, g = i & 15;
        const float4* src = ((const float4*)(Kg + ((size_t)(b * LK + kr)) * HIDD + h * DD)) + g;
        cp16(sbase + (uint32_t)((kr * 16 + (g ^ (kr & 7))) * 16), src);
    }
    asm volatile("cp.async.commit_group;");

    const ulonglong2* qb2 = (const ulonglong2*)qbuf;
    const ulonglong2* db2 = (const ulonglong2*)dbuf;
    const int qb = w * 4;
    const int s  = lane & 7;
    float sume[4] = {0.f, 0.f, 0.f, 0.f};

    for (int c = 0; c < 16; c++) {
        if (c + 1 < 16) {
            uint32_t boff = (uint32_t)(((c + 1) & 1) * 32768);
            #pragma unroll
            for (int r = 0; r < 8; r++) {
                int i = tid + 256 * r; int kr = i >> 4, g = i & 15;
                const float4* src = ((const float4*)(Kg +
                    ((size_t)(b * LK + (c + 1) * 128 + kr)) * HIDD + h * DD)) + g;
                cp16(sbase + boff + (uint32_t)((kr * 16 + (g ^ (kr & 7))) * 16), src);
            }
            asm volatile("cp.async.commit_group;");
            asm volatile("cp.async.wait_group 1;");
        } else {
            asm volatile("cp.async.wait_group 0;");
        }
        __syncthreads();

        const ulonglong2* kb2 = (const ulonglong2*)(smem + (c & 1) * 8192);

        u64 acc[4][4];
        #pragma unroll
        for (int q = 0; q < 4; q++)
            #pragma unroll
            for (int kk = 0; kk < 4; kk++) acc[q][kk] = 0ull;

        #pragma unroll 4
        for (int g = 0; g < 16; g++) {
            ulonglong2 dv = db2[g];
            ulonglong2 qv[4];
            #pragma unroll
            for (int q = 0; q < 4; q++) qv[q] = qb2[(qb + q) * 16 + g];
            #pragma unroll
            for (int kk = 0; kk < 4; kk++) {
                ulonglong2 kv = kb2[(kk * 32 + lane) * 16 + (g ^ s)];
                #pragma unroll
                for (int q = 0; q < 4; q++) {
                    u64 t0 = fadd2(kv.x, qv[q].x) & ABSM;   // |k - q| (q pre-negated)
                    u64 t1 = fadd2(kv.y, qv[q].y) & ABSM;
                    acc[q][kk] = ffma2(dv.x, t0, acc[q][kk]);
                    acc[q][kk] = ffma2(dv.y, t1, acc[q][kk]);
                }
            }
        }

        #pragma unroll
        for (int q = 0; q < 4; q++) {
            size_t base = (((size_t)(b * NH + h)) * LQ + (q0 + qb + q)) * (size_t)LK + c * 128;
            #pragma unroll
            for (int kk = 0; kk < 4; kk++) {
                float2 a = upk2(acc[q][kk]);
                float e = __expf((CENTER_C - (a.x + a.y)) * INV_SCALING_C);
                attn[base + kk * 32 + lane] = e;
                sume[q] += e;
            }
        }
        __syncthreads();
    }

    #pragma unroll
    for (int q = 0; q < 4; q++) {
        float ssum = sume[q];
        #pragma unroll
        for (int o = 16; o > 0; o >>= 1) ssum += __shfl_xor_sync(0xffffffffu, ssum, o);
        if (lane == 0)
            g_rsum[((size_t)(b * NH + h)) * LQ + q0 + qb + q] = 1.f / ssum;
    }
}

// ---------------------------------------------------------------------------
// Kernel 2: single pass — P = e * inv_sum (write back) + P @ V.
//   grid (LQ/32, NH, BB), block 256. vT rows loaded coalesced from g_VT
//   (stride 164 words: 16B aligned + conflict-free LDS.128). P@V packed f32x2
//   over k-pairs; p loads are smem broadcasts.
// ---------------------------------------------------------------------------
#define VSTR 164

__global__ __launch_bounds__(256) void k_softpv(
    float* __restrict__ attn, float* __restrict__ out0)
{
    extern __shared__ float smem[];
    float* vT  = smem;                    // 64 x VSTR
    float* psm = smem + 64 * VSTR;        // 32 q x 128 k
    float* inv = psm + 32 * 128;          // 32

    const int b  = blockIdx.z, h = blockIdx.y;
    const int q0 = blockIdx.x * 32;
    const int tid = threadIdx.x, w = tid >> 5, lane = tid & 31;
    const int qb = w * 4;

    if (tid < 32) inv[tid] = g_rsum[((size_t)(b * NH + h)) * LQ + q0 + tid];
    __syncthreads();

    u64 acc[4][2];
    #pragma unroll
    for (int q = 0; q < 4; q++) { acc[q][0] = 0ull; acc[q][1] = 0ull; }

    const float* vtb = g_VT + ((size_t)(b * NH + h)) * DD * LK;

    for (int kc = 0; kc < LK; kc += 128) {
        // load V^T chunk: row d gets k[kc..kc+127], coalesced LDG + conflict-free STS
        #pragma unroll
        for (int r = 0; r < 8; r++) {
            int j = tid + 256 * r; int d = j >> 5, k4 = j & 31;
            float4 v = *(const float4*)(vtb + (size_t)d * LK + kc + 4 * k4);
            *(float4*)(vT + d * VSTR + 4 * k4) = v;
        }
        // normalize: p = e * inv, write back to gmem + stash in smem
        #pragma unroll
        for (int r = 0; r < 4; r++) {
            int j = tid + 256 * r; int q = j >> 5, k4 = j & 31;
            size_t idx = (((size_t)(b * NH + h)) * LQ + q0 + q) * (size_t)LK + kc + 4 * k4;
            float4 e = *(const float4*)(attn + idx);
            float iv = inv[q];
            float4 p = make_float4(e.x * iv, e.y * iv, e.z * iv, e.w * iv);
            *(float4*)(attn + idx) = p;
            *(float4*)(psm + q * 128 + 4 * k4) = p;
        }
        __syncthreads();

        // P @ V: lane = d (two halves), packed f32x2 over k-pairs
        #pragma unroll 8
        for (int k4 = 0; k4 < 32; k4++) {
            ulonglong2 v0 = *(const ulonglong2*)(vT + lane * VSTR + 4 * k4);
            ulonglong2 v1 = *(const ulonglong2*)(vT + (lane + 32) * VSTR + 4 * k4);
            #pragma unroll
            for (int q = 0; q < 4; q++) {
                ulonglong2 pp = *(const ulonglong2*)(psm + (qb + q) * 128 + 4 * k4);
                acc[q][0] = ffma2(pp.x, v0.x, acc[q][0]);
                acc[q][0] = ffma2(pp.y, v0.y, acc[q][0]);
                acc[q][1] = ffma2(pp.x, v1.x, acc[q][1]);
                acc[q][1] = ffma2(pp.y, v1.y, acc[q][1]);
            }
        }
        __syncthreads();
    }

    #pragma unroll
    for (int q = 0; q < 4; q++) {
        float2 a0 = upk2(acc[q][0]);
        float2 a1 = upk2(acc[q][1]);
        size_t ob = ((size_t)(b * LQ + q0 + qb + q)) * HIDD + h * DD;
        out0[ob + lane]      = a0.x + a0.y;
        out0[ob + 32 + lane] = a1.x + a1.y;
    }
}

#define SMEM1 ((8192 * 2 + 2048 + 64) * 4)              /* 73984 B */
#define SMEM2 ((64 * VSTR + 32 * 128 + 32) * 4)         /* 58496 B */

extern "C" void kernel_launch(void* const* d_in, const int* in_sizes, int n_in,
                              void* d_out, int out_size)
{
    const float* Qg = (const float*)d_in[0];
    const float* Kg = (const float*)d_in[1];
    const float* Vg = (const float*)d_in[2];
    const float* dg = (const float*)d_in[3];

    float* out0 = (float*)d_out;
    float* attn = out0 + (size_t)BB * LQ * HIDD;   // (output, attention) concat

    cudaFuncSetAttribute(k_logits, cudaFuncAttributeMaxDynamicSharedMemorySize, SMEM1);
    cudaFuncSetAttribute(k_softpv, cudaFuncAttributeMaxDynamicSharedMemorySize, SMEM2);

    dim3 grid(LQ / 32, NH, BB);
    k_vtrans<<<dim3(LK / 64, BB * NH), 256>>>(Vg);
    k_logits<<<grid, 256, SMEM1>>>(Qg, Kg, dg, attn);
    k_softpv<<<grid, 256, SMEM2>>>(attn, out0);
}